// round 16
// baseline (speedup 1.0000x reference)
#include <cuda_runtime.h>
#include <cuda_fp16.h>
#include <cstdint>

#define NN 100000
#define EMAX 1600000
#define GS_BLOCKS 2368          // 16 CTAs/SM * 148 SMs
#define GS_THREADS 256
#define SB 256
#define NSB ((NN + SB - 1) / SB)   // 391 scan blocks

// -------- scratch (static device globals; no runtime allocation) --------
__device__ __align__(16) int    g_pos32[2 * EMAX];
__device__ __align__(16) int    g_csr[EMAX];       // neighbor col ids grouped by row
__device__ __align__(16) int    g_ideg[NN];        // zero-initialized at load; decode re-zeros
__device__ __align__(16) int    g_partial[NSB];
__device__ __align__(16) int    g_offs[NN + 1];
__device__ __align__(16) int    g_cursor[NN];
__device__ __align__(16) float  g_dis[NN];
__device__ __align__(16) __half g_xh[NN * 256];    // fp16 copy of x
__device__ __align__(16) __half g_w1h[256 * 64];
__device__ __align__(16) __half g_w2h[64 * 64];
__device__ __align__(16) __half g_h[NN * 64];      // fp16: x@W1+b1   (no dis)
__device__ __align__(16) __half g_acc1[NN * 64];   // fp16: relu(dis-weighted agg)
__device__ __align__(16) __half g_t[NN * 64];      // fp16: dis[i]*(acc1@W2+b2)
__device__ __align__(16) __half g_z[NN * 64];      // fp16 z (decode-only consumer)
__device__ int g_is64;

// Fused prep: fp32->fp16 convert of x/W1/W2 (DRAM-BW bound) + pos->int32 +
// degree count (latency/atomic bound — hides under the convert stream).
__global__ void prep_kernel(const float* __restrict__ x, long long nx,
                            const float* __restrict__ W1, int nw1,
                            const float* __restrict__ W2, int nw2,
                            __half* __restrict__ xh,
                            __half* __restrict__ w1h,
                            __half* __restrict__ w2h,
                            const unsigned int* __restrict__ pos,
                            int* __restrict__ pos32,
                            int* __restrict__ ideg, long long twoE) {
    int myok = 1;
    if (threadIdx.x < 64 && pos[2 * threadIdx.x + 1] != 0u) myok = 0;
    int is64 = __syncthreads_and(myok);
    if (threadIdx.x == 0 && blockIdx.x == 0) g_is64 = is64;

    long long i0 = (long long)blockIdx.x * blockDim.x + threadIdx.x;
    long long stride = (long long)gridDim.x * blockDim.x;

    long long E = twoE >> 1;
    if (is64) {
        const long long* p64 = (const long long*)pos;
        for (long long i = i0; i < twoE; i += stride) {
            int pv = (int)p64[i];
            pos32[i] = pv;
            if (i < E) atomicAdd(&ideg[pv], 1);
        }
    } else {
        const int* p32 = (const int*)pos;
        for (long long i = i0; i < twoE; i += stride) {
            int pv = p32[i];
            pos32[i] = pv;
            if (i < E) atomicAdd(&ideg[pv], 1);
        }
    }

    const float4* x4 = (const float4*)x;
    long long n4 = nx >> 2;
    for (long long i = i0; i < n4; i += stride) {
        float4 f = x4[i];
        __half2 a = __floats2half2_rn(f.x, f.y);
        __half2 b = __floats2half2_rn(f.z, f.w);
        ((uint2*)xh)[i] = make_uint2(*(unsigned int*)&a, *(unsigned int*)&b);
    }
    for (long long i = i0; i < nw1; i += stride) w1h[i] = __float2half(W1[i]);
    for (long long i = i0; i < nw2; i += stride) w2h[i] = __float2half(W2[i]);
}

// scan1: per-block (256 nodes) degree sums -> partial[b].
__global__ void scan1_kernel(const int* __restrict__ ideg, int* __restrict__ partial,
                             int n) {
    __shared__ int sh[SB];
    int t = threadIdx.x;
    int i = blockIdx.x * SB + t;
    sh[t] = (i < n) ? ideg[i] : 0;
    __syncthreads();
#pragma unroll
    for (int off = SB / 2; off > 0; off >>= 1) {
        if (t < off) sh[t] += sh[t + off];
        __syncthreads();
    }
    if (t == 0) partial[blockIdx.x] = sh[0];
}

// scan3: block b computes base = sum(partial[0..b)), intra-block exclusive scan.
__global__ void scan3_kernel(const int* __restrict__ ideg,
                             const int* __restrict__ partial,
                             int* __restrict__ offs, int* __restrict__ cursor,
                             float* __restrict__ dis, int n) {
    __shared__ int sh[SB];
    int t = threadIdx.x;
    int b = blockIdx.x;

    int ps = 0;
    for (int i = t; i < b; i += SB) ps += partial[i];
    sh[t] = ps;
    __syncthreads();
#pragma unroll
    for (int off = SB / 2; off > 0; off >>= 1) {
        if (t < off) sh[t] += sh[t + off];
        __syncthreads();
    }
    int base = sh[0];
    __syncthreads();

    int i = b * SB + t;
    int d = (i < n) ? ideg[i] : 0;
    sh[t] = d;
    __syncthreads();
#pragma unroll
    for (int off = 1; off < SB; off <<= 1) {
        int v = (t >= off) ? sh[t - off] : 0;
        __syncthreads();
        sh[t] += v;
        __syncthreads();
    }
    int excl = sh[t] - d;
    if (i < n) {
        int run = base + excl;
        offs[i] = run;
        cursor[i] = run;
        dis[i] = (d > 0) ? rsqrtf((float)d) : 0.0f;
        if (i == n - 1) offs[n] = run + d;
    }
}

__global__ void fill_kernel(const int* __restrict__ pos, long long E,
                            int* cursor, int* csr) {
    long long stride = (long long)gridDim.x * blockDim.x;
    for (long long e = (long long)blockIdx.x * blockDim.x + threadIdx.x;
         e < E; e += stride) {
        int row = pos[e];
        int col = pos[E + e];
        int slot = atomicAdd(&cursor[row], 1);
        csr[slot] = col;
    }
}

// ---------------- common async helpers ----------------
#define SWZ(b)   ((b) ^ (((b) >> 3) & 0x70))   // 128B rows

__device__ __forceinline__ uint32_t smem_u32(const void* p) {
    return (uint32_t)__cvta_generic_to_shared(p);
}
__device__ __forceinline__ void cp16(uint32_t dst, const void* src, bool pred) {
    int sz = pred ? 16 : 0;
    asm volatile("cp.async.cg.shared.global [%0], [%1], 16, %2;"
                 :: "r"(dst), "l"(src), "r"(sz));
}
__device__ __forceinline__ void cp_commit() {
    asm volatile("cp.async.commit_group;");
}
template <int N>
__device__ __forceinline__ void cp_wait() {
    asm volatile("cp.async.wait_group %0;" :: "n"(N));
}
__device__ __forceinline__ void ldsm4(uint32_t& r0, uint32_t& r1,
                                      uint32_t& r2, uint32_t& r3, uint32_t a) {
    asm volatile("ldmatrix.sync.aligned.m8n8.x4.shared.b16 {%0,%1,%2,%3}, [%4];"
                 : "=r"(r0), "=r"(r1), "=r"(r2), "=r"(r3) : "r"(a));
}
__device__ __forceinline__ void ldsm4t(uint32_t& r0, uint32_t& r1,
                                       uint32_t& r2, uint32_t& r3, uint32_t a) {
    asm volatile("ldmatrix.sync.aligned.m8n8.x4.trans.shared.b16 {%0,%1,%2,%3}, [%4];"
                 : "=r"(r0), "=r"(r1), "=r"(r2), "=r"(r3) : "r"(a));
}
__device__ __forceinline__ void mma16816(float* d,
                                         uint32_t a0, uint32_t a1, uint32_t a2, uint32_t a3,
                                         uint32_t b0, uint32_t b1) {
    asm volatile("mma.sync.aligned.m16n8k16.row.col.f32.f16.f16.f32 "
                 "{%0,%1,%2,%3}, {%4,%5,%6,%7}, {%8,%9}, {%0,%1,%2,%3};"
                 : "+f"(d[0]), "+f"(d[1]), "+f"(d[2]), "+f"(d[3])
                 : "r"(a0), "r"(a1), "r"(a2), "r"(a3), "r"(b0), "r"(b1));
}

// Yh[row,:64] = fp16( s * (Xh[row,:K] @ Wh[K,64] + b) )  where
// s = dis[row] if dis != nullptr else 1.
__global__ void __launch_bounds__(256, 3)
gemm_mma_kernel(const __half* __restrict__ Xh,
                const __half* __restrict__ Wh,
                const float* __restrict__ bias,
                const float* __restrict__ dis,
                __half* __restrict__ Yh,
                int n, int K) {
    __shared__ __align__(16) __half xs[2][128 * 64];
    __shared__ __align__(16) __half Ws[2][64 * 64];

    int t = threadIdx.x;
    int warp = t >> 5;
    int lane = t & 31;
    int row0 = blockIdx.x * 128;

    float acc[8][4];
#pragma unroll
    for (int f = 0; f < 8; f++)
#pragma unroll
        for (int i = 0; i < 4; i++) acc[f][i] = 0.0f;

    int srow = t >> 1;
    int kh = (t & 1) * 32;
    int grow = row0 + srow;
    bool rvalid = grow < n;
    int wk = t >> 2;
    int nh = (t & 3) * 16;

    uint32_t xs_b[2] = { smem_u32(xs[0]), smem_u32(xs[1]) };
    uint32_t ws_b[2] = { smem_u32(Ws[0]), smem_u32(Ws[1]) };

    int nchunks = K >> 6;

    auto issue = [&](int kb, int buf) {
        const __half* xsrc = Xh + (long long)grow * K + kb * 64 + kh;
#pragma unroll
        for (int i = 0; i < 4; i++)
            cp16(xs_b[buf] + SWZ(srow * 128 + kh * 2 + 16 * i), xsrc + 8 * i, rvalid);
        const __half* wsrc = Wh + (long long)(kb * 64 + wk) * 64 + nh;
#pragma unroll
        for (int i = 0; i < 2; i++)
            cp16(ws_b[buf] + SWZ(wk * 128 + nh * 2 + 16 * i), wsrc + 8 * i, true);
        cp_commit();
    };

    issue(0, 0);
    if (nchunks > 1) issue(1, 1);

    int arow = warp * 16 + (lane & 15);
    int acol = (lane >> 4) * 8;
    int brl = lane & 15;
    int bcol = (lane >> 4) * 8;

    for (int kb = 0; kb < nchunks; kb++) {
        int cur = kb & 1;
        if (kb + 1 < nchunks) cp_wait<1>(); else cp_wait<0>();
        __syncthreads();

#pragma unroll
        for (int s = 0; s < 4; s++) {
            uint32_t a0, a1, a2, a3;
            ldsm4(a0, a1, a2, a3,
                  xs_b[cur] + SWZ(arow * 128 + (s * 16 + acol) * 2));
            int brow = s * 16 + brl;
#pragma unroll
            for (int i = 0; i < 4; i++) {
                uint32_t b0, b1, b2, b3;
                ldsm4t(b0, b1, b2, b3,
                       ws_b[cur] + SWZ(brow * 128 + (i * 16 + bcol) * 2));
                mma16816(acc[2 * i],     a0, a1, a2, a3, b0, b1);
                mma16816(acc[2 * i + 1], a0, a1, a2, a3, b2, b3);
            }
        }

        if (kb + 2 < nchunks) {
            __syncthreads();
            issue(kb + 2, cur);
        }
    }

    int g = lane >> 2;
    int tig = lane & 3;
    int rowA = row0 + warp * 16 + g;
    int rowB = rowA + 8;
    float sA = 1.0f, sB = 1.0f;
    if (dis) {
        sA = (rowA < n) ? dis[rowA] : 0.0f;
        sB = (rowB < n) ? dis[rowB] : 0.0f;
    }
#pragma unroll
    for (int f = 0; f < 8; f++) {
        int c = f * 8 + tig * 2;
        float bx = __ldg(bias + c);
        float by = __ldg(bias + c + 1);
        if (rowA < n) {
            __half2 o = __floats2half2_rn((acc[f][0] + bx) * sA,
                                          (acc[f][1] + by) * sA);
            *(__half2*)(Yh + (long long)rowA * 64 + c) = o;
        }
        if (rowB < n) {
            __half2 o = __floats2half2_rn((acc[f][2] + bx) * sB,
                                          (acc[f][3] + by) * sB);
            *(__half2*)(Yh + (long long)rowB * 64 + c) = o;
        }
    }
}

__device__ __forceinline__ void fmau4(float acc[8], uint4 u, float w) {
    const __half2* p = (const __half2*)&u;
#pragma unroll
    for (int t = 0; t < 4; t++) {
        float2 f = __half22float2(p[t]);
        acc[2 * t]     += w * f.x;
        acc[2 * t + 1] += w * f.y;
    }
}

// Gather v6: cp.async-pipelined. Warp per node; neighbor rows staged into
// smem in 8-row batches, 3 stages (3 KB/warp, 24 KB/CTA -> 8 CTAs/SM).
// Per warp ~2 KB of global reads in flight => latency fully covered.
// Smem layout: slot j of row r stored at col ((j+r)&7) -> conflict-free LDS.128.
// use_dis: weight = dis[c] (layer 1) or 1 (layer 2 — dis folded into gemm2).
__global__ void __launch_bounds__(256)
gather_kernel(const int* __restrict__ offs,
              const int* __restrict__ csr,
              const float* __restrict__ dis,
              const __half* __restrict__ H,
              __half* __restrict__ out,
              int n, int do_relu, int use_dis) {
    __shared__ __align__(16) char pipe[8][3][1024];   // [warp][stage][8 rows x 128B]

    int lane = threadIdx.x & 31;
    int w = threadIdx.x >> 5;
    int q = lane >> 3;           // quarter 0..3
    int j = lane & 7;            // uint4 slot within the 64-half row
    long long warp0 = ((long long)blockIdx.x * blockDim.x + threadIdx.x) >> 5;
    long long nwarps = ((long long)gridDim.x * blockDim.x) >> 5;
    const uint4* H8 = (const uint4*)H;
    uint32_t sbase = smem_u32(pipe[w]);

    // cp slots this lane stages per batch: slot and slot+32 of 64 (8 rows x 8 cols)
    int s0r = lane >> 3,        s0j = lane & 7;         // rows 0..3
    int s1r = (lane >> 3) + 4,  s1j = lane & 7;         // rows 4..7

    for (long long node = warp0; node < n; node += nwarps) {
        int s = offs[node];
        int e = offs[node + 1];
        int last = (e > s) ? e - 1 : s;                 // safe clamp target
        int nb = (e - s + 7) >> 3;

        float acc[8];
#pragma unroll
        for (int i = 0; i < 8; i++) acc[i] = 0.0f;

        auto issue = [&](int b, int stage) {
            if (b < nb) {
                int base = s + 8 * b;
                uint32_t dst = sbase + stage * 1024;
                int c0 = csr[min(base + s0r, last)];
                int c1 = csr[min(base + s1r, last)];
                cp16(dst + s0r * 128 + (((s0j + s0r) & 7) << 4),
                     H8 + (long long)c0 * 8 + s0j, true);
                cp16(dst + s1r * 128 + (((s1j + s1r) & 7) << 4),
                     H8 + (long long)c1 * 8 + s1j, true);
            }
            cp_commit();
        };

        issue(0, 0);
        issue(1, 1);

        for (int b = 0; b < nb; b++) {
            cp_wait<1>();           // batch b landed (b+1 may be pending)
            int st = b % 3;
            uint32_t sb = sbase + st * 1024;

            int idxA = s + 8 * b + q;       // row q
            int idxB = idxA + 4;            // row q+4
            int cA = csr[min(idxA, last)];
            int cB = csr[min(idxB, last)];
            float wA = (idxA < e) ? (use_dis ? dis[cA] : 1.f) : 0.f;
            float wB = (idxB < e) ? (use_dis ? dis[cB] : 1.f) : 0.f;

            uint4 uA, uB;
            uint32_t aA = sb + q * 128 + (((j + q) & 7) << 4);
            uint32_t aB = sb + (q + 4) * 128 + (((j + q + 4) & 7) << 4);
            asm volatile("ld.shared.v4.u32 {%0,%1,%2,%3},[%4];"
                         : "=r"(uA.x), "=r"(uA.y), "=r"(uA.z), "=r"(uA.w) : "r"(aA));
            asm volatile("ld.shared.v4.u32 {%0,%1,%2,%3},[%4];"
                         : "=r"(uB.x), "=r"(uB.y), "=r"(uB.z), "=r"(uB.w) : "r"(aB));
            fmau4(acc, uA, wA);
            fmau4(acc, uB, wB);

            issue(b + 2, (b + 2) % 3);
        }

        // combine the 4 quarters
#pragma unroll
        for (int i = 0; i < 8; i++) {
            acc[i] += __shfl_xor_sync(0xffffffffu, acc[i], 8);
            acc[i] += __shfl_xor_sync(0xffffffffu, acc[i], 16);
        }

        if (q == 0) {
            float dr = dis[node];
#pragma unroll
            for (int i = 0; i < 8; i++) acc[i] *= dr;
            if (do_relu) {
#pragma unroll
                for (int i = 0; i < 8; i++) acc[i] = fmaxf(acc[i], 0.f);
            }
            __half2 hh[4];
#pragma unroll
            for (int t = 0; t < 4; t++)
                hh[t] = __floats2half2_rn(acc[2 * t], acc[2 * t + 1]);
            uint4 pk;
            pk.x = *(unsigned int*)&hh[0]; pk.y = *(unsigned int*)&hh[1];
            pk.z = *(unsigned int*)&hh[2]; pk.w = *(unsigned int*)&hh[3];
            ((uint4*)out)[node * 8 + j] = pk;
        }
    }
}

// Decode: 8 lanes/edge, 4 edges per group per iter => 8 independent LDG.128
// per lane in flight. Tail duty: re-zero g_ideg for the next replay.
__global__ void decode_kernel(const int* __restrict__ pos,
                              const void* __restrict__ negv, long long E,
                              const __half* __restrict__ Zh, float* __restrict__ out,
                              int* __restrict__ ideg, int n) {
    long long tid = (long long)blockIdx.x * blockDim.x + threadIdx.x;
    if (tid < n) ideg[tid] = 0;     // reset degrees for next replay

    int is64 = g_is64;
    const long long* n64 = (const long long*)negv;
    const int* n32 = (const int*)negv;

    int lane = threadIdx.x & 31;
    int grp = lane >> 3;
    int j = lane & 7;
    long long warp0 = tid >> 5;
    long long nwarps = ((long long)gridDim.x * blockDim.x) >> 5;
    long long twoE = 2 * E;
    const uint4* Z8 = (const uint4*)Zh;

    for (long long w16 = warp0 * 16; w16 < twoE; w16 += nwarps * 16) {
        long long wid[4];
        bool v[4];
        uint4 ua[4], ub[4];
#pragma unroll
        for (int u = 0; u < 4; u++) {
            long long w = w16 + 4 * u + grp;
            v[u] = w < twoE;
            wid[u] = w;
            long long wc = v[u] ? w : 0;
            int a, b;
            if (wc < E) {
                a = pos[wc];
                b = pos[E + wc];
            } else if (is64) {
                a = (int)n64[wc - E];
                b = (int)n64[wc];
            } else {
                a = n32[wc - E];
                b = n32[wc];
            }
            ua[u] = Z8[(long long)a * 8 + j];
            ub[u] = Z8[(long long)b * 8 + j];
        }
#pragma unroll
        for (int u = 0; u < 4; u++) {
            const __half2* pa = (const __half2*)&ua[u];
            const __half2* pb = (const __half2*)&ub[u];
            float s = 0.f;
#pragma unroll
            for (int t = 0; t < 4; t++) {
                float2 fa = __half22float2(pa[t]);
                float2 fb = __half22float2(pb[t]);
                s += fa.x * fb.x + fa.y * fb.y;
            }
            s += __shfl_xor_sync(0xffffffffu, s, 1);
            s += __shfl_xor_sync(0xffffffffu, s, 2);
            s += __shfl_xor_sync(0xffffffffu, s, 4);
            if (j == 0 && v[u]) out[wid[u]] = s;
        }
    }
}

extern "C" void kernel_launch(void* const* d_in, const int* in_sizes, int n_in,
                              void* d_out, int out_size) {
    const float* x   = (const float*)d_in[0];
    const void*  pos = d_in[1];
    const void*  neg = d_in[2];
    const float* W1  = (const float*)d_in[3];
    const float* b1  = (const float*)d_in[4];
    const float* W2  = (const float*)d_in[5];
    const float* b2  = (const float*)d_in[6];
    float* out = (float*)d_out;

    long long E = (long long)in_sizes[1] / 2;   // 1.6M
    int n = NN;
    int Fin = in_sizes[0] / n;                  // 256

    int *pos32, *csr, *ideg, *partial, *offs, *cursor;
    float *dis;
    __half *xh, *w1h, *w2h, *h, *acc1, *t, *z;
    cudaGetSymbolAddress((void**)&pos32,   g_pos32);
    cudaGetSymbolAddress((void**)&csr,     g_csr);
    cudaGetSymbolAddress((void**)&ideg,    g_ideg);
    cudaGetSymbolAddress((void**)&partial, g_partial);
    cudaGetSymbolAddress((void**)&offs,    g_offs);
    cudaGetSymbolAddress((void**)&cursor,  g_cursor);
    cudaGetSymbolAddress((void**)&dis,     g_dis);
    cudaGetSymbolAddress((void**)&xh,      g_xh);
    cudaGetSymbolAddress((void**)&w1h,     g_w1h);
    cudaGetSymbolAddress((void**)&w2h,     g_w2h);
    cudaGetSymbolAddress((void**)&h,       g_h);
    cudaGetSymbolAddress((void**)&acc1,    g_acc1);
    cudaGetSymbolAddress((void**)&t,       g_t);
    cudaGetSymbolAddress((void**)&z,       g_z);

    static cudaStream_t sSide = 0;
    static cudaEvent_t eFork = 0, eJoin = 0;
    if (!sSide) {
        cudaStreamCreateWithFlags(&sSide, cudaStreamNonBlocking);
        cudaEventCreateWithFlags(&eFork, cudaEventDisableTiming);
        cudaEventCreateWithFlags(&eJoin, cudaEventDisableTiming);
    }

    int gblocks = (n + 127) / 128;

    prep_kernel<<<GS_BLOCKS, GS_THREADS>>>(
        x, (long long)n * Fin, W1, Fin * 64, W2, 64 * 64, xh, w1h, w2h,
        (const unsigned int*)pos, pos32, ideg, 2 * E);

    // fork: gemm1 (depends only on prep; no dis) overlaps scan + fill
    cudaEventRecord(eFork, 0);
    cudaStreamWaitEvent(sSide, eFork, 0);
    gemm_mma_kernel<<<gblocks, 256, 0, sSide>>>(xh, w1h, b1, (const float*)0,
                                                h, n, Fin);
    cudaEventRecord(eJoin, sSide);

    scan1_kernel<<<NSB, SB>>>(ideg, partial, n);
    scan3_kernel<<<NSB, SB>>>(ideg, partial, offs, cursor, dis, n);
    fill_kernel<<<GS_BLOCKS, GS_THREADS>>>(pos32, E, cursor, csr);

    cudaStreamWaitEvent(0, eJoin, 0);
    gather_kernel<<<GS_BLOCKS, GS_THREADS>>>(offs, csr, dis, h, acc1, n, 1, 1);
    gemm_mma_kernel<<<gblocks, 256>>>(acc1, w2h, b2, dis, t, n, 64);
    gather_kernel<<<GS_BLOCKS, GS_THREADS>>>(offs, csr, dis, t, z, n, 0, 0);

    decode_kernel<<<GS_BLOCKS, GS_THREADS>>>(pos32, neg, E, z, out, ideg, n);
}

// round 17
// speedup vs baseline: 1.1210x; 1.1210x over previous
#include <cuda_runtime.h>
#include <cuda_fp16.h>
#include <cstdint>

#define NN 100000
#define EMAX 1600000
#define GS_BLOCKS 2368          // 16 CTAs/SM * 148 SMs
#define GS_THREADS 256
#define SB 256
#define NSB ((NN + SB - 1) / SB)   // 391 scan blocks

// -------- scratch (static device globals; no runtime allocation) --------
__device__ __align__(16) int    g_pos32[2 * EMAX];
__device__ __align__(16) int    g_csr[EMAX];       // neighbor col ids grouped by row
__device__ __align__(16) int    g_ideg[NN];        // zero-initialized at load; decode re-zeros
__device__ __align__(16) int    g_partial[NSB];
__device__ __align__(16) int    g_offs[NN + 1];
__device__ __align__(16) int    g_cursor[NN];
__device__ __align__(16) float  g_dis[NN];
__device__ __align__(16) __half g_xh[NN * 256];    // fp16 copy of x
__device__ __align__(16) __half g_w1h[256 * 64];
__device__ __align__(16) __half g_w2h[64 * 64];
__device__ __align__(16) __half g_h[NN * 64];      // fp16: x@W1+b1   (no dis)
__device__ __align__(16) __half g_acc1[NN * 64];   // fp16: relu(dis-weighted agg)
__device__ __align__(16) __half g_t[NN * 64];      // fp16: dis[i]*(acc1@W2+b2)
__device__ __align__(16) __half g_z[NN * 64];      // fp16 z (decode-only consumer)
__device__ int g_is64;

// Fused prep: fp32->fp16 convert of x/W1/W2 (DRAM-BW bound) + pos->int32 +
// degree count (latency/atomic bound — hides under the convert stream).
__global__ void prep_kernel(const float* __restrict__ x, long long nx,
                            const float* __restrict__ W1, int nw1,
                            const float* __restrict__ W2, int nw2,
                            __half* __restrict__ xh,
                            __half* __restrict__ w1h,
                            __half* __restrict__ w2h,
                            const unsigned int* __restrict__ pos,
                            int* __restrict__ pos32,
                            int* __restrict__ ideg, long long twoE) {
    int myok = 1;
    if (threadIdx.x < 64 && pos[2 * threadIdx.x + 1] != 0u) myok = 0;
    int is64 = __syncthreads_and(myok);
    if (threadIdx.x == 0 && blockIdx.x == 0) g_is64 = is64;

    long long i0 = (long long)blockIdx.x * blockDim.x + threadIdx.x;
    long long stride = (long long)gridDim.x * blockDim.x;

    long long E = twoE >> 1;
    if (is64) {
        const long long* p64 = (const long long*)pos;
        for (long long i = i0; i < twoE; i += stride) {
            int pv = (int)p64[i];
            pos32[i] = pv;
            if (i < E) atomicAdd(&ideg[pv], 1);
        }
    } else {
        const int* p32 = (const int*)pos;
        for (long long i = i0; i < twoE; i += stride) {
            int pv = p32[i];
            pos32[i] = pv;
            if (i < E) atomicAdd(&ideg[pv], 1);
        }
    }

    const float4* x4 = (const float4*)x;
    long long n4 = nx >> 2;
    for (long long i = i0; i < n4; i += stride) {
        float4 f = x4[i];
        __half2 a = __floats2half2_rn(f.x, f.y);
        __half2 b = __floats2half2_rn(f.z, f.w);
        ((uint2*)xh)[i] = make_uint2(*(unsigned int*)&a, *(unsigned int*)&b);
    }
    for (long long i = i0; i < nw1; i += stride) w1h[i] = __float2half(W1[i]);
    for (long long i = i0; i < nw2; i += stride) w2h[i] = __float2half(W2[i]);
}

// scan1: per-block (256 nodes) degree sums -> partial[b].
__global__ void scan1_kernel(const int* __restrict__ ideg, int* __restrict__ partial,
                             int n) {
    __shared__ int sh[SB];
    int t = threadIdx.x;
    int i = blockIdx.x * SB + t;
    sh[t] = (i < n) ? ideg[i] : 0;
    __syncthreads();
#pragma unroll
    for (int off = SB / 2; off > 0; off >>= 1) {
        if (t < off) sh[t] += sh[t + off];
        __syncthreads();
    }
    if (t == 0) partial[blockIdx.x] = sh[0];
}

// scan3: block b computes base = sum(partial[0..b)), intra-block exclusive scan.
__global__ void scan3_kernel(const int* __restrict__ ideg,
                             const int* __restrict__ partial,
                             int* __restrict__ offs, int* __restrict__ cursor,
                             float* __restrict__ dis, int n) {
    __shared__ int sh[SB];
    int t = threadIdx.x;
    int b = blockIdx.x;

    int ps = 0;
    for (int i = t; i < b; i += SB) ps += partial[i];
    sh[t] = ps;
    __syncthreads();
#pragma unroll
    for (int off = SB / 2; off > 0; off >>= 1) {
        if (t < off) sh[t] += sh[t + off];
        __syncthreads();
    }
    int base = sh[0];
    __syncthreads();

    int i = b * SB + t;
    int d = (i < n) ? ideg[i] : 0;
    sh[t] = d;
    __syncthreads();
#pragma unroll
    for (int off = 1; off < SB; off <<= 1) {
        int v = (t >= off) ? sh[t - off] : 0;
        __syncthreads();
        sh[t] += v;
        __syncthreads();
    }
    int excl = sh[t] - d;
    if (i < n) {
        int run = base + excl;
        offs[i] = run;
        cursor[i] = run;
        dis[i] = (d > 0) ? rsqrtf((float)d) : 0.0f;
        if (i == n - 1) offs[n] = run + d;
    }
}

__global__ void fill_kernel(const int* __restrict__ pos, long long E,
                            int* cursor, int* csr) {
    long long stride = (long long)gridDim.x * blockDim.x;
    for (long long e = (long long)blockIdx.x * blockDim.x + threadIdx.x;
         e < E; e += stride) {
        int row = pos[e];
        int col = pos[E + e];
        int slot = atomicAdd(&cursor[row], 1);
        csr[slot] = col;
    }
}

// ---------------- common async helpers ----------------
#define SWZ(b)   ((b) ^ (((b) >> 3) & 0x70))   // 128B rows

__device__ __forceinline__ uint32_t smem_u32(const void* p) {
    return (uint32_t)__cvta_generic_to_shared(p);
}
__device__ __forceinline__ void cp16(uint32_t dst, const void* src, bool pred) {
    int sz = pred ? 16 : 0;
    asm volatile("cp.async.cg.shared.global [%0], [%1], 16, %2;"
                 :: "r"(dst), "l"(src), "r"(sz));
}
__device__ __forceinline__ void cp_commit() {
    asm volatile("cp.async.commit_group;");
}
template <int N>
__device__ __forceinline__ void cp_wait() {
    asm volatile("cp.async.wait_group %0;" :: "n"(N));
}
__device__ __forceinline__ void ldsm4(uint32_t& r0, uint32_t& r1,
                                      uint32_t& r2, uint32_t& r3, uint32_t a) {
    asm volatile("ldmatrix.sync.aligned.m8n8.x4.shared.b16 {%0,%1,%2,%3}, [%4];"
                 : "=r"(r0), "=r"(r1), "=r"(r2), "=r"(r3) : "r"(a));
}
__device__ __forceinline__ void ldsm4t(uint32_t& r0, uint32_t& r1,
                                       uint32_t& r2, uint32_t& r3, uint32_t a) {
    asm volatile("ldmatrix.sync.aligned.m8n8.x4.trans.shared.b16 {%0,%1,%2,%3}, [%4];"
                 : "=r"(r0), "=r"(r1), "=r"(r2), "=r"(r3) : "r"(a));
}
__device__ __forceinline__ void mma16816(float* d,
                                         uint32_t a0, uint32_t a1, uint32_t a2, uint32_t a3,
                                         uint32_t b0, uint32_t b1) {
    asm volatile("mma.sync.aligned.m16n8k16.row.col.f32.f16.f16.f32 "
                 "{%0,%1,%2,%3}, {%4,%5,%6,%7}, {%8,%9}, {%0,%1,%2,%3};"
                 : "+f"(d[0]), "+f"(d[1]), "+f"(d[2]), "+f"(d[3])
                 : "r"(a0), "r"(a1), "r"(a2), "r"(a3), "r"(b0), "r"(b1));
}

// Yh[row,:64] = fp16( s * (Xh[row,:K] @ Wh[K,64] + b) )  where
// s = dis[row] if dis != nullptr else 1.
__global__ void __launch_bounds__(256, 3)
gemm_mma_kernel(const __half* __restrict__ Xh,
                const __half* __restrict__ Wh,
                const float* __restrict__ bias,
                const float* __restrict__ dis,
                __half* __restrict__ Yh,
                int n, int K) {
    __shared__ __align__(16) __half xs[2][128 * 64];
    __shared__ __align__(16) __half Ws[2][64 * 64];

    int t = threadIdx.x;
    int warp = t >> 5;
    int lane = t & 31;
    int row0 = blockIdx.x * 128;

    float acc[8][4];
#pragma unroll
    for (int f = 0; f < 8; f++)
#pragma unroll
        for (int i = 0; i < 4; i++) acc[f][i] = 0.0f;

    int srow = t >> 1;
    int kh = (t & 1) * 32;
    int grow = row0 + srow;
    bool rvalid = grow < n;
    int wk = t >> 2;
    int nh = (t & 3) * 16;

    uint32_t xs_b[2] = { smem_u32(xs[0]), smem_u32(xs[1]) };
    uint32_t ws_b[2] = { smem_u32(Ws[0]), smem_u32(Ws[1]) };

    int nchunks = K >> 6;

    auto issue = [&](int kb, int buf) {
        const __half* xsrc = Xh + (long long)grow * K + kb * 64 + kh;
#pragma unroll
        for (int i = 0; i < 4; i++)
            cp16(xs_b[buf] + SWZ(srow * 128 + kh * 2 + 16 * i), xsrc + 8 * i, rvalid);
        const __half* wsrc = Wh + (long long)(kb * 64 + wk) * 64 + nh;
#pragma unroll
        for (int i = 0; i < 2; i++)
            cp16(ws_b[buf] + SWZ(wk * 128 + nh * 2 + 16 * i), wsrc + 8 * i, true);
        cp_commit();
    };

    issue(0, 0);
    if (nchunks > 1) issue(1, 1);

    int arow = warp * 16 + (lane & 15);
    int acol = (lane >> 4) * 8;
    int brl = lane & 15;
    int bcol = (lane >> 4) * 8;

    for (int kb = 0; kb < nchunks; kb++) {
        int cur = kb & 1;
        if (kb + 1 < nchunks) cp_wait<1>(); else cp_wait<0>();
        __syncthreads();

#pragma unroll
        for (int s = 0; s < 4; s++) {
            uint32_t a0, a1, a2, a3;
            ldsm4(a0, a1, a2, a3,
                  xs_b[cur] + SWZ(arow * 128 + (s * 16 + acol) * 2));
            int brow = s * 16 + brl;
#pragma unroll
            for (int i = 0; i < 4; i++) {
                uint32_t b0, b1, b2, b3;
                ldsm4t(b0, b1, b2, b3,
                       ws_b[cur] + SWZ(brow * 128 + (i * 16 + bcol) * 2));
                mma16816(acc[2 * i],     a0, a1, a2, a3, b0, b1);
                mma16816(acc[2 * i + 1], a0, a1, a2, a3, b2, b3);
            }
        }

        if (kb + 2 < nchunks) {
            __syncthreads();
            issue(kb + 2, cur);
        }
    }

    int g = lane >> 2;
    int tig = lane & 3;
    int rowA = row0 + warp * 16 + g;
    int rowB = rowA + 8;
    float sA = 1.0f, sB = 1.0f;
    if (dis) {
        sA = (rowA < n) ? dis[rowA] : 0.0f;
        sB = (rowB < n) ? dis[rowB] : 0.0f;
    }
#pragma unroll
    for (int f = 0; f < 8; f++) {
        int c = f * 8 + tig * 2;
        float bx = __ldg(bias + c);
        float by = __ldg(bias + c + 1);
        if (rowA < n) {
            __half2 o = __floats2half2_rn((acc[f][0] + bx) * sA,
                                          (acc[f][1] + by) * sA);
            *(__half2*)(Yh + (long long)rowA * 64 + c) = o;
        }
        if (rowB < n) {
            __half2 o = __floats2half2_rn((acc[f][2] + bx) * sB,
                                          (acc[f][3] + by) * sB);
            *(__half2*)(Yh + (long long)rowB * 64 + c) = o;
        }
    }
}

__device__ __forceinline__ void fmau4(float acc[8], uint4 u, float w) {
    const __half2* p = (const __half2*)&u;
#pragma unroll
    for (int t = 0; t < 4; t++) {
        float2 f = __half22float2(p[t]);
        acc[2 * t]     += w * f.x;
        acc[2 * t + 1] += w * f.y;
    }
}

// Gather v7: each 8-lane group owns ONE node (4 nodes per warp concurrently).
// 4-neighbor batches per group => 4 independent H-row LDG.128 per lane in
// flight, batch waste E[ceil(d/4)*4 - d] ~ 12% (vs 50% at 16-granularity).
// No cross-group shfl combine: the group's 8 lanes hold the complete row.
// use_dis: weight = dis[c] (layer 1) or 1 (layer 2 — dis folded into gemm2).
__global__ void gather_kernel(const int* __restrict__ offs,
                              const int* __restrict__ csr,
                              const float* __restrict__ dis,
                              const __half* __restrict__ H,
                              __half* __restrict__ out,
                              int n, int do_relu, int use_dis) {
    int lane = threadIdx.x & 31;
    int g = lane >> 3;           // group 0..3 within warp
    int j = lane & 7;            // uint4 slot within the 64-half row
    long long warp0 = ((long long)blockIdx.x * blockDim.x + threadIdx.x) >> 5;
    long long nwarps = ((long long)gridDim.x * blockDim.x) >> 5;
    const uint4* H8 = (const uint4*)H;

    for (long long node = warp0 * 4 + g; node < n; node += nwarps * 4) {
        int s = offs[node];
        int e = offs[node + 1];
        float acc[8];
#pragma unroll
        for (int i = 0; i < 8; i++) acc[i] = 0.0f;

        for (int base = s; base < e; base += 4) {
            int last = e - 1;
            int i0 = base + 0, i1 = base + 1, i2 = base + 2, i3 = base + 3;
            int c0 = csr[i0];              // i0 < e always
            int c1 = csr[min(i1, last)];
            int c2 = csr[min(i2, last)];
            int c3 = csr[min(i3, last)];
            float w0, w1, w2, w3;
            if (use_dis) {
                w0 = dis[c0];
                w1 = (i1 < e) ? dis[c1] : 0.f;
                w2 = (i2 < e) ? dis[c2] : 0.f;
                w3 = (i3 < e) ? dis[c3] : 0.f;
            } else {
                w0 = 1.f;
                w1 = (i1 < e) ? 1.f : 0.f;
                w2 = (i2 < e) ? 1.f : 0.f;
                w3 = (i3 < e) ? 1.f : 0.f;
            }
            uint4 u0 = H8[(long long)c0 * 8 + j];
            uint4 u1 = H8[(long long)c1 * 8 + j];
            uint4 u2 = H8[(long long)c2 * 8 + j];
            uint4 u3 = H8[(long long)c3 * 8 + j];
            fmau4(acc, u0, w0);
            fmau4(acc, u1, w1);
            fmau4(acc, u2, w2);
            fmau4(acc, u3, w3);
        }

        float dr = dis[node];
#pragma unroll
        for (int i = 0; i < 8; i++) acc[i] *= dr;
        if (do_relu) {
#pragma unroll
            for (int i = 0; i < 8; i++) acc[i] = fmaxf(acc[i], 0.f);
        }
        __half2 hh[4];
#pragma unroll
        for (int t = 0; t < 4; t++)
            hh[t] = __floats2half2_rn(acc[2 * t], acc[2 * t + 1]);
        uint4 pk;
        pk.x = *(unsigned int*)&hh[0]; pk.y = *(unsigned int*)&hh[1];
        pk.z = *(unsigned int*)&hh[2]; pk.w = *(unsigned int*)&hh[3];
        ((uint4*)out)[node * 8 + j] = pk;
    }
}

// Decode: 8 lanes/edge, 4 edges per group per iter => 8 independent LDG.128
// per lane in flight. Tail duty: re-zero g_ideg for the next replay.
__global__ void decode_kernel(const int* __restrict__ pos,
                              const void* __restrict__ negv, long long E,
                              const __half* __restrict__ Zh, float* __restrict__ out,
                              int* __restrict__ ideg, int n) {
    long long tid = (long long)blockIdx.x * blockDim.x + threadIdx.x;
    if (tid < n) ideg[tid] = 0;     // reset degrees for next replay

    int is64 = g_is64;
    const long long* n64 = (const long long*)negv;
    const int* n32 = (const int*)negv;

    int lane = threadIdx.x & 31;
    int grp = lane >> 3;
    int j = lane & 7;
    long long warp0 = tid >> 5;
    long long nwarps = ((long long)gridDim.x * blockDim.x) >> 5;
    long long twoE = 2 * E;
    const uint4* Z8 = (const uint4*)Zh;

    for (long long w16 = warp0 * 16; w16 < twoE; w16 += nwarps * 16) {
        long long wid[4];
        bool v[4];
        uint4 ua[4], ub[4];
#pragma unroll
        for (int u = 0; u < 4; u++) {
            long long w = w16 + 4 * u + grp;
            v[u] = w < twoE;
            wid[u] = w;
            long long wc = v[u] ? w : 0;
            int a, b;
            if (wc < E) {
                a = pos[wc];
                b = pos[E + wc];
            } else if (is64) {
                a = (int)n64[wc - E];
                b = (int)n64[wc];
            } else {
                a = n32[wc - E];
                b = n32[wc];
            }
            ua[u] = Z8[(long long)a * 8 + j];
            ub[u] = Z8[(long long)b * 8 + j];
        }
#pragma unroll
        for (int u = 0; u < 4; u++) {
            const __half2* pa = (const __half2*)&ua[u];
            const __half2* pb = (const __half2*)&ub[u];
            float s = 0.f;
#pragma unroll
            for (int t = 0; t < 4; t++) {
                float2 fa = __half22float2(pa[t]);
                float2 fb = __half22float2(pb[t]);
                s += fa.x * fb.x + fa.y * fb.y;
            }
            s += __shfl_xor_sync(0xffffffffu, s, 1);
            s += __shfl_xor_sync(0xffffffffu, s, 2);
            s += __shfl_xor_sync(0xffffffffu, s, 4);
            if (j == 0 && v[u]) out[wid[u]] = s;
        }
    }
}

extern "C" void kernel_launch(void* const* d_in, const int* in_sizes, int n_in,
                              void* d_out, int out_size) {
    const float* x   = (const float*)d_in[0];
    const void*  pos = d_in[1];
    const void*  neg = d_in[2];
    const float* W1  = (const float*)d_in[3];
    const float* b1  = (const float*)d_in[4];
    const float* W2  = (const float*)d_in[5];
    const float* b2  = (const float*)d_in[6];
    float* out = (float*)d_out;

    long long E = (long long)in_sizes[1] / 2;   // 1.6M
    int n = NN;
    int Fin = in_sizes[0] / n;                  // 256

    int *pos32, *csr, *ideg, *partial, *offs, *cursor;
    float *dis;
    __half *xh, *w1h, *w2h, *h, *acc1, *t, *z;
    cudaGetSymbolAddress((void**)&pos32,   g_pos32);
    cudaGetSymbolAddress((void**)&csr,     g_csr);
    cudaGetSymbolAddress((void**)&ideg,    g_ideg);
    cudaGetSymbolAddress((void**)&partial, g_partial);
    cudaGetSymbolAddress((void**)&offs,    g_offs);
    cudaGetSymbolAddress((void**)&cursor,  g_cursor);
    cudaGetSymbolAddress((void**)&dis,     g_dis);
    cudaGetSymbolAddress((void**)&xh,      g_xh);
    cudaGetSymbolAddress((void**)&w1h,     g_w1h);
    cudaGetSymbolAddress((void**)&w2h,     g_w2h);
    cudaGetSymbolAddress((void**)&h,       g_h);
    cudaGetSymbolAddress((void**)&acc1,    g_acc1);
    cudaGetSymbolAddress((void**)&t,       g_t);
    cudaGetSymbolAddress((void**)&z,       g_z);

    static cudaStream_t sSide = 0;
    static cudaEvent_t eFork = 0, eJoin = 0;
    if (!sSide) {
        cudaStreamCreateWithFlags(&sSide, cudaStreamNonBlocking);
        cudaEventCreateWithFlags(&eFork, cudaEventDisableTiming);
        cudaEventCreateWithFlags(&eJoin, cudaEventDisableTiming);
    }

    int gblocks = (n + 127) / 128;

    prep_kernel<<<GS_BLOCKS, GS_THREADS>>>(
        x, (long long)n * Fin, W1, Fin * 64, W2, 64 * 64, xh, w1h, w2h,
        (const unsigned int*)pos, pos32, ideg, 2 * E);

    // fork: gemm1 (depends only on prep; no dis) overlaps scan + fill
    cudaEventRecord(eFork, 0);
    cudaStreamWaitEvent(sSide, eFork, 0);
    gemm_mma_kernel<<<gblocks, 256, 0, sSide>>>(xh, w1h, b1, (const float*)0,
                                                h, n, Fin);
    cudaEventRecord(eJoin, sSide);

    scan1_kernel<<<NSB, SB>>>(ideg, partial, n);
    scan3_kernel<<<NSB, SB>>>(ideg, partial, offs, cursor, dis, n);
    fill_kernel<<<GS_BLOCKS, GS_THREADS>>>(pos32, E, cursor, csr);

    cudaStreamWaitEvent(0, eJoin, 0);
    gather_kernel<<<GS_BLOCKS, GS_THREADS>>>(offs, csr, dis, h, acc1, n, 1, 1);
    gemm_mma_kernel<<<gblocks, 256>>>(acc1, w2h, b2, dis, t, n, 64);
    gather_kernel<<<GS_BLOCKS, GS_THREADS>>>(offs, csr, dis, t, z, n, 0, 0);

    decode_kernel<<<GS_BLOCKS, GS_THREADS>>>(pos32, neg, E, z, out, ideg, n);
}